// round 1
// baseline (speedup 1.0000x reference)
#include <cuda_runtime.h>
#include <cuda_bf16.h>
#include <math.h>

// ---------------------------------------------------------------------------
// GCN + TopK pooling stack (3 layers), B=128 graphs, N=1024 nodes, H=128.
// K1=512, K2=256, K3=128. E edges fixed (masked after pooling).
// All fp32. Output: [B, 2H] = 128 x 256 floats.
// ---------------------------------------------------------------------------

#define Bg   128
#define Npg  1024
#define Hd   128
#define NN1  (Bg*Npg)        // 131072
#define NN2  (Bg*512)        // 65536
#define NN3  (Bg*256)        // 32768
#define EMAX 1048576

// ------------------------- device scratch (no allocs) ----------------------
__device__ float g_h [NN1*Hd];        // h = x @ W
__device__ float g_cv[NN1*Hd];        // conv output / relu'd x for pooling
__device__ float g_xs1[NN2*Hd];       // pooled features after layer 1
__device__ float g_xs2[NN3*Hd];       // pooled features after layer 2
__device__ float g_xs3[(Bg*128)*Hd];  // pooled features after layer 3
__device__ float g_dinv[NN1];         // deg then rsqrt(deg)
__device__ float g_sc[NN1];           // node scores
__device__ int   g_newid[NN1];
__device__ int   g_r0[EMAX], g_c0[EMAX];
__device__ float g_m0[EMAX];
__device__ int   g_r1[EMAX], g_c1[EMAX];
__device__ float g_m1[EMAX];
__device__ float g_pinv;              // 1/||p||

// ------------------------------- GEMM --------------------------------------
// Out[n,128] = X[n,128] @ W[128,128].  64-row tiles, W fully in smem.
#define GEMM_SMEM ((128*128 + 64*129) * 4)

__global__ void __launch_bounds__(256, 2)
gemm128(const float* __restrict__ X, const float* __restrict__ W,
        float* __restrict__ Out)
{
    extern __shared__ float sh[];
    float* sW = sh;               // [128][128]
    float* sX = sh + 128*128;     // [64][129] (pad kills bank conflicts)
    const int t = threadIdx.x;
    const long row0 = (long)blockIdx.x * 64;

    for (int i = t; i < 4096; i += 256) {             // W: 4096 float4
        float4 v = ((const float4*)W)[i];
        int off = i * 4;
        sW[off] = v.x; sW[off+1] = v.y; sW[off+2] = v.z; sW[off+3] = v.w;
    }
    for (int i = t; i < 2048; i += 256) {             // X tile: 2048 float4
        int r = i >> 5, c4 = i & 31;
        float4 v = ((const float4*)(X + (row0 + r) * Hd))[c4];
        float* d = sX + r * 129 + c4 * 4;
        d[0] = v.x; d[1] = v.y; d[2] = v.z; d[3] = v.w;
    }
    __syncthreads();

    const int r  = t >> 2;
    const int cg = (t & 3) * 32;
    float acc[32];
#pragma unroll
    for (int j = 0; j < 32; j++) acc[j] = 0.f;
    const float* xr = sX + r * 129;
#pragma unroll 8
    for (int k = 0; k < 128; k++) {
        float a = xr[k];
        const float* wr = sW + k * 128 + cg;
#pragma unroll
        for (int j = 0; j < 32; j++) acc[j] = fmaf(a, wr[j], acc[j]);
    }
    float* o = Out + (row0 + r) * Hd + cg;
#pragma unroll
    for (int j = 0; j < 32; j += 4)
        *((float4*)(o + j)) = make_float4(acc[j], acc[j+1], acc[j+2], acc[j+3]);
}

// --------------------------- degree / dinv ---------------------------------
__global__ void fill1_k(float* d, int n) {
    int i = blockIdx.x * blockDim.x + threadIdx.x;
    if (i < n) d[i] = 1.0f;
}
__global__ void deg_acc_k(const int* __restrict__ col,
                          const float* __restrict__ mask, float* deg, int nE) {
    int i = blockIdx.x * blockDim.x + threadIdx.x;
    if (i >= nE) return;
    float m = mask ? mask[i] : 1.0f;
    if (m != 0.0f) atomicAdd(&deg[col[i]], m);
}
__global__ void to_dinv_k(float* d, int n) {
    int i = blockIdx.x * blockDim.x + threadIdx.x;
    if (i < n) d[i] = rsqrtf(d[i]);
}

// ------------------ self-loop term + bias: out = h*dinv^2 + b --------------
__global__ void self_init_k(const float* __restrict__ h,
                            const float* __restrict__ dinv,
                            const float* __restrict__ b,
                            float* __restrict__ out, int n) {
    int idx = blockIdx.x * blockDim.x + threadIdx.x;   // over n*32 float4s
    if (idx >= n * 32) return;
    int node = idx >> 5, c4 = idx & 31;
    float d  = dinv[node];
    float dd = d * d;
    float4 hv = ((const float4*)h)[idx];
    float4 bv = ((const float4*)b)[c4];
    ((float4*)out)[idx] = make_float4(fmaf(hv.x, dd, bv.x), fmaf(hv.y, dd, bv.y),
                                      fmaf(hv.z, dd, bv.z), fmaf(hv.w, dd, bv.w));
}

// --------------------- edge scatter: out[col] += h[row]*coef ---------------
__global__ void edge_agg_k(const int* __restrict__ row, const int* __restrict__ col,
                           const float* __restrict__ mask,
                           const float* __restrict__ dinv,
                           const float* __restrict__ h,
                           float* __restrict__ out, int nE) {
    int w = (blockIdx.x * blockDim.x + threadIdx.x) >> 5;  // one warp per edge
    if (w >= nE) return;
    int lane = threadIdx.x & 31;
    float m = mask ? mask[w] : 1.0f;
    if (m == 0.0f) return;
    int r = row[w], c = col[w];
    float coef = dinv[r] * dinv[c] * m;
    float4 v = ((const float4*)(h + (long)r * Hd))[lane];
    v.x *= coef; v.y *= coef; v.z *= coef; v.w *= coef;
    atomicAdd(((float4*)(out + (long)c * Hd)) + lane, v);  // RED.128, sm_90+
}

// ------------------------------- relu --------------------------------------
__global__ void relu_k(float* x, int n4) {
    int i = blockIdx.x * blockDim.x + threadIdx.x;
    if (i >= n4) return;
    float4 v = ((float4*)x)[i];
    v.x = fmaxf(v.x, 0.f); v.y = fmaxf(v.y, 0.f);
    v.z = fmaxf(v.z, 0.f); v.w = fmaxf(v.w, 0.f);
    ((float4*)x)[i] = v;
}

// ------------------------------ scores -------------------------------------
__global__ void pnorm_k(const float* __restrict__ p) {     // <<<1,128>>>
    __shared__ float s[128];
    float v = p[threadIdx.x];
    s[threadIdx.x] = v * v;
    __syncthreads();
    for (int o = 64; o > 0; o >>= 1) {
        if (threadIdx.x < o) s[threadIdx.x] += s[threadIdx.x + o];
        __syncthreads();
    }
    if (threadIdx.x == 0) g_pinv = 1.0f / sqrtf(s[0]);
}
__global__ void score_k(const float* __restrict__ x, const float* __restrict__ p,
                        float* __restrict__ score, int n) {
    int w = (blockIdx.x * blockDim.x + threadIdx.x) >> 5;  // warp per node
    if (w >= n) return;
    int lane = threadIdx.x & 31;
    float4 v = ((const float4*)(x + (long)w * Hd))[lane];
    float4 q = ((const float4*)p)[lane];
    float s = v.x*q.x + v.y*q.y + v.z*q.z + v.w*q.w;
#pragma unroll
    for (int o = 16; o; o >>= 1) s += __shfl_xor_sync(0xffffffffu, s, o);
    if (lane == 0) score[w] = s * g_pinv;
}

// --------------------- top-k (matches jax.lax.top_k) ------------------------
// One block per graph, blockDim = n_per (power of 2). Bitonic sort of packed
// keys: ascending key == descending score, tie -> ascending index.
__global__ void topk_k(const float* __restrict__ x, const float* __restrict__ score,
                       float* __restrict__ xs, int* __restrict__ newid,
                       int n_per, int k) {
    __shared__ unsigned long long keys[1024];
    int g = blockIdx.x, t = threadIdx.x;
    int base = g * n_per;

    newid[base + t] = -1;
    float s = score[base + t];
    unsigned int fb = __float_as_uint(s);
    unsigned int mp = (fb & 0x80000000u) ? ~fb : (fb | 0x80000000u); // order-preserving
    keys[t] = ((unsigned long long)(~mp) << 32) | (unsigned int)t;
    __syncthreads();

    for (int kk = 2; kk <= n_per; kk <<= 1) {
        for (int j = kk >> 1; j > 0; j >>= 1) {
            int ixj = t ^ j;
            if (ixj > t) {
                bool up = ((t & kk) == 0);
                unsigned long long a = keys[t], b = keys[ixj];
                if ((a > b) == up) { keys[t] = b; keys[ixj] = a; }
            }
            __syncthreads();
        }
    }

    if (t < k) {
        int sel = (int)(keys[t] & 0xffffffffu);
        newid[base + sel] = g * k + t;
    }
    __syncthreads();

    int total = k * Hd;
    for (int idx = t; idx < total; idx += n_per) {
        int rank = idx >> 7, f = idx & 127;
        int sel = (int)(keys[rank] & 0xffffffffu);
        float tv = tanhf(score[base + sel]);
        xs[((long)(g * k + rank)) * Hd + f] = x[((long)(base + sel)) * Hd + f] * tv;
    }
}

// --------------------------- edge relabel ----------------------------------
__global__ void relabel_k(const int* __restrict__ row, const int* __restrict__ col,
                          const float* __restrict__ mask, const int* __restrict__ newid,
                          int* __restrict__ nrow, int* __restrict__ ncol,
                          float* __restrict__ nmask, int nE) {
    int e = blockIdx.x * blockDim.x + threadIdx.x;
    if (e >= nE) return;
    int nr = newid[row[e]], nc = newid[col[e]];
    float m = mask ? mask[e] : 1.0f;
    if (nr < 0 || nc < 0) m = 0.0f;
    nrow[e] = nr > 0 ? nr : 0;
    ncol[e] = nc > 0 ? nc : 0;
    nmask[e] = m;
}

// ------------------------------ readout ------------------------------------
__global__ void readout_k(const float* __restrict__ xs, float* __restrict__ out,
                          int k, int add) {                // <<<B,128>>>
    int g = blockIdx.x, f = threadIdx.x;
    float mx = -3.402823466e+38f, sm = 0.f;
    const float* p = xs + (long)g * k * Hd + f;
    for (int r = 0; r < k; r++) {
        float v = p[(long)r * Hd];
        mx = fmaxf(mx, v);
        sm += v;
    }
    float mean = sm / (float)k;
    if (add) { out[g*256 + f] += mx; out[g*256 + 128 + f] += mean; }
    else     { out[g*256 + f]  = mx; out[g*256 + 128 + f]  = mean; }
}

// ------------------------------- driver ------------------------------------
static inline int ceil_div(int a, int b) { return (a + b - 1) / b; }

static void run_layer(const float* xin, int n, int nper, int k,
                      const int* erow, const int* ecol, const float* emask,
                      const float* W, const float* b, const float* p,
                      float* h, float* cv, float* dinv, float* score, int* newid,
                      float* xs_out,
                      int* nrow, int* ncol, float* nmask,
                      int E, float* out, int addFlag)
{
    gemm128<<<n / 64, 256, GEMM_SMEM>>>(xin, W, h);
    fill1_k<<<ceil_div(n, 256), 256>>>(dinv, n);
    deg_acc_k<<<ceil_div(E, 256), 256>>>(ecol, emask, dinv, E);
    to_dinv_k<<<ceil_div(n, 256), 256>>>(dinv, n);
    self_init_k<<<ceil_div(n * 32, 256), 256>>>(h, dinv, b, cv, n);
    edge_agg_k<<<ceil_div(E * 32, 256), 256>>>(erow, ecol, emask, dinv, h, cv, E);
    relu_k<<<ceil_div(n * 32, 256), 256>>>(cv, n * 32);
    pnorm_k<<<1, 128>>>(p);
    score_k<<<ceil_div(n * 32, 256), 256>>>(cv, p, score, n);
    topk_k<<<Bg, nper>>>(cv, score, xs_out, newid, nper, k);
    if (nrow)
        relabel_k<<<ceil_div(E, 256), 256>>>(erow, ecol, emask, newid,
                                             nrow, ncol, nmask, E);
    readout_k<<<Bg, 128>>>(xs_out, out, k, addFlag);
}

extern "C" void kernel_launch(void* const* d_in, const int* in_sizes, int n_in,
                              void* d_out, int out_size)
{
    const float* x    = (const float*)d_in[0];
    const int*   erow = (const int*)  d_in[1];
    const int*   ecol = (const int*)  d_in[2];
    const float* W1 = (const float*)d_in[3],  *b1 = (const float*)d_in[4],  *p1 = (const float*)d_in[5];
    const float* W2 = (const float*)d_in[6],  *b2 = (const float*)d_in[7],  *p2 = (const float*)d_in[8];
    const float* W3 = (const float*)d_in[9],  *b3 = (const float*)d_in[10], *p3 = (const float*)d_in[11];
    float* out = (float*)d_out;
    const int E = in_sizes[1];

    // resolve scratch symbols (host API, outside graph replay cost)
    float *h, *cv, *xs1, *xs2, *xs3, *dinv, *sc, *m0, *m1;
    int *nid, *r0, *c0, *r1, *c1;
    cudaGetSymbolAddress((void**)&h,    g_h);
    cudaGetSymbolAddress((void**)&cv,   g_cv);
    cudaGetSymbolAddress((void**)&xs1,  g_xs1);
    cudaGetSymbolAddress((void**)&xs2,  g_xs2);
    cudaGetSymbolAddress((void**)&xs3,  g_xs3);
    cudaGetSymbolAddress((void**)&dinv, g_dinv);
    cudaGetSymbolAddress((void**)&sc,   g_sc);
    cudaGetSymbolAddress((void**)&nid,  g_newid);
    cudaGetSymbolAddress((void**)&r0,   g_r0);
    cudaGetSymbolAddress((void**)&c0,   g_c0);
    cudaGetSymbolAddress((void**)&m0,   g_m0);
    cudaGetSymbolAddress((void**)&r1,   g_r1);
    cudaGetSymbolAddress((void**)&c1,   g_c1);
    cudaGetSymbolAddress((void**)&m1,   g_m1);

    cudaFuncSetAttribute(gemm128, cudaFuncAttributeMaxDynamicSharedMemorySize,
                         GEMM_SMEM);

    // Layer 1: 131072 nodes, 1024/graph -> keep 512
    run_layer(x, NN1, 1024, 512, erow, ecol, /*mask=*/nullptr,
              W1, b1, p1, h, cv, dinv, sc, nid, xs1,
              r0, c0, m0, E, out, /*add=*/0);
    // Layer 2: 65536 nodes, 512/graph -> keep 256
    run_layer(xs1, NN2, 512, 256, r0, c0, m0,
              W2, b2, p2, h, cv, dinv, sc, nid, xs2,
              r1, c1, m1, E, out, /*add=*/1);
    // Layer 3: 32768 nodes, 256/graph -> keep 128 (no edge relabel needed)
    run_layer(xs2, NN3, 256, 128, r1, c1, m1,
              W3, b3, p3, h, cv, dinv, sc, nid, xs3,
              nullptr, nullptr, nullptr, E, out, /*add=*/1);
}

// round 2
// speedup vs baseline: 4.7627x; 4.7627x over previous
#include <cuda_runtime.h>
#include <cuda_bf16.h>
#include <math.h>

// ---------------------------------------------------------------------------
// GCN + TopK pooling stack (3 layers), B=128 graphs, N=1024 nodes, H=128.
// K1=512, K2=256, K3=128. E edges fixed (masked after pooling).
// All fp32. Output: [B, 2H] = 128 x 256 floats.
// ---------------------------------------------------------------------------

#define Bg   128
#define Npg  1024
#define Hd   128
#define NN1  (Bg*Npg)        // 131072
#define NN2  (Bg*512)        // 65536
#define NN3  (Bg*256)        // 32768
#define EMAX 1048576

// ------------------------- device scratch (no allocs) ----------------------
__device__ __align__(128) float g_h [NN1*Hd];   // h = x @ W
__device__ __align__(128) float g_cv[NN1*Hd];   // conv output (relu'd)
__device__ __align__(128) float g_xs1[NN2*Hd];  // pooled features after layer 1
__device__ __align__(128) float g_xs2[NN3*Hd];  // pooled features after layer 2
__device__ __align__(128) float g_xs3[(Bg*128)*Hd];
__device__ float g_dinv[NN1];
__device__ float g_sc[NN1];
__device__ int   g_newid[NN1];
__device__ int   g_cnt[NN1];      // in-degree counts (masked)
__device__ int   g_start[NN1];    // CSR start offsets
__device__ int   g_cursor[NN1];   // fill cursors
__device__ int   g_bsum[256];     // scan block sums
__device__ int   g_src[EMAX];     // CSR source-node list
__device__ int   g_r0[EMAX], g_c0[EMAX];
__device__ float g_m0[EMAX];
__device__ int   g_r1[EMAX], g_c1[EMAX];
__device__ float g_m1[EMAX];
__device__ float g_pinv;          // 1/||p||

// ------------------------------ f32x2 helpers -------------------------------
__device__ __forceinline__ unsigned long long pack2(float x) {
    unsigned long long r;
    asm("mov.b64 %0, {%1, %1};" : "=l"(r) : "f"(x));
    return r;
}
__device__ __forceinline__ unsigned long long pack2(float x, float y) {
    unsigned long long r;
    asm("mov.b64 %0, {%1, %2};" : "=l"(r) : "f"(x), "f"(y));
    return r;
}
__device__ __forceinline__ void fma2(unsigned long long& d,
                                     unsigned long long a, unsigned long long b) {
    asm("fma.rn.f32x2 %0, %1, %2, %0;" : "+l"(d) : "l"(a), "l"(b));
}

// ------------------------------- GEMM --------------------------------------
// Out[n,128] = X[n,128] @ W[128,128]. 128-row tiles, 256 threads, 8x8 micro.
// k-major smem chunks of 16, pad 132 -> conflict-free compute loads.
#define KP 132

__global__ void __launch_bounds__(256, 2)
gemm128(const float* __restrict__ X, const float* __restrict__ W,
        float* __restrict__ Out)
{
    __shared__ float sX[16][KP];   // [k][row]
    __shared__ float sW[16][KP];   // [k][col]
    const int tid = threadIdx.x;
    const int tx = tid & 15;       // column group: cols tx*4..+3 and 64+tx*4..+3
    const int ty = tid >> 4;       // row group: rows ty*8..+7
    const long row0 = (long)blockIdx.x * 128;

    unsigned long long acc[8][4];
#pragma unroll
    for (int i = 0; i < 8; i++)
#pragma unroll
        for (int j = 0; j < 4; j++) acc[i][j] = 0ull;

    for (int k0 = 0; k0 < 128; k0 += 16) {
        // stage W chunk: W[k0+kk][c] -> sW[kk][c]; 512 float4, 2 per thread
#pragma unroll
        for (int q = 0; q < 2; q++) {
            int f = tid + q * 256;
            int kk = f >> 5, c4 = f & 31;
            float4 v = ((const float4*)(W + (k0 + kk) * 128))[c4];
            float* d = &sW[kk][c4 * 4];
            d[0] = v.x; d[1] = v.y; d[2] = v.z; d[3] = v.w;
        }
        // stage X chunk transposed: X[row0+r][k0+kq*4..] -> sX[k][r]
#pragma unroll
        for (int q = 0; q < 2; q++) {
            int f = tid + q * 256;
            int r = f >> 2, kq = (f & 3) * 4;
            float4 v = ((const float4*)(X + (row0 + r) * 128 + k0))[f & 3];
            sX[kq + 0][r] = v.x; sX[kq + 1][r] = v.y;
            sX[kq + 2][r] = v.z; sX[kq + 3][r] = v.w;
        }
        __syncthreads();

#pragma unroll
        for (int k = 0; k < 16; k++) {
            float4 b0 = *(const float4*)&sW[k][tx * 4];
            float4 b1 = *(const float4*)&sW[k][64 + tx * 4];
            float4 a0 = *(const float4*)&sX[k][ty * 8];
            float4 a1 = *(const float4*)&sX[k][ty * 8 + 4];
            unsigned long long B[4] = { pack2(b0.x, b0.y), pack2(b0.z, b0.w),
                                        pack2(b1.x, b1.y), pack2(b1.z, b1.w) };
            float av[8] = { a0.x, a0.y, a0.z, a0.w, a1.x, a1.y, a1.z, a1.w };
#pragma unroll
            for (int i = 0; i < 8; i++) {
                unsigned long long A = pack2(av[i]);
                fma2(acc[i][0], A, B[0]);
                fma2(acc[i][1], A, B[1]);
                fma2(acc[i][2], A, B[2]);
                fma2(acc[i][3], A, B[3]);
            }
        }
        __syncthreads();
    }

#pragma unroll
    for (int i = 0; i < 8; i++) {
        float* o = Out + (row0 + ty * 8 + i) * 128;
        *((float4*)(o + tx * 4))      = *(float4*)&acc[i][0];
        *((float4*)(o + 64 + tx * 4)) = *(float4*)&acc[i][2];
    }
}

// ------------------------- CSR build: hist / scan / fill --------------------
__global__ void hist_k(const int* __restrict__ col, const float* __restrict__ mask,
                       int* __restrict__ cnt, int nE) {
    int i = blockIdx.x * blockDim.x + threadIdx.x;
    if (i >= nE) return;
    if (!mask || mask[i] != 0.0f) atomicAdd(&cnt[col[i]], 1);
}

__global__ void scanA_k(const int* __restrict__ cnt, int* __restrict__ start,
                        int* __restrict__ bsum) {
    __shared__ int s[1024];
    int t = threadIdx.x;
    int i = blockIdx.x * 1024 + t;
    int v = cnt[i];
    s[t] = v;
    __syncthreads();
    for (int o = 1; o < 1024; o <<= 1) {
        int add = (t >= o) ? s[t - o] : 0;
        __syncthreads();
        s[t] += add;
        __syncthreads();
    }
    start[i] = s[t] - v;                  // exclusive within block
    if (t == 1023) bsum[blockIdx.x] = s[t];
}

__global__ void scanB_k(int* bsum, int nb) {   // <<<1,128>>>, nb <= 128
    __shared__ int s[128];
    int t = threadIdx.x;
    int v = (t < nb) ? bsum[t] : 0;
    s[t] = v;
    __syncthreads();
    for (int o = 1; o < 128; o <<= 1) {
        int add = (t >= o) ? s[t - o] : 0;
        __syncthreads();
        s[t] += add;
        __syncthreads();
    }
    if (t < nb) bsum[t] = s[t] - v;       // exclusive
}

__global__ void scanC_k(int* __restrict__ start, const int* __restrict__ bsum,
                        const int* __restrict__ cnt, float* __restrict__ dinv, int n) {
    int i = blockIdx.x * blockDim.x + threadIdx.x;
    if (i >= n) return;
    start[i] += bsum[i >> 10];
    dinv[i] = rsqrtf((float)cnt[i] + 1.0f);
}

__global__ void fill_k(const int* __restrict__ row, const int* __restrict__ col,
                       const float* __restrict__ mask, const int* __restrict__ start,
                       int* __restrict__ cursor, int* __restrict__ src, int nE) {
    int i = blockIdx.x * blockDim.x + threadIdx.x;
    if (i >= nE) return;
    if (mask && mask[i] == 0.0f) return;
    int c = col[i];
    int p = atomicAdd(&cursor[c], 1);
    src[start[c] + p] = row[i];
}

// ---- gather + self-loop + bias + relu fused: one warp per destination node --
__global__ void gather_k(const float* __restrict__ h, const int* __restrict__ start,
                         const int* __restrict__ cnt, const int* __restrict__ src,
                         const float* __restrict__ dinv, const float* __restrict__ b,
                         float* __restrict__ out, int n) {
    int w = (blockIdx.x * blockDim.x + threadIdx.x) >> 5;
    if (w >= n) return;
    int lane = threadIdx.x & 31;
    float dc = dinv[w];
    int s0 = start[w], d = cnt[w];
    float4 hv = ((const float4*)(h + (long)w * Hd))[lane];
    float4 bv = ((const float4*)b)[lane];
    float dd = dc * dc;
    float4 acc = make_float4(fmaf(hv.x, dd, bv.x), fmaf(hv.y, dd, bv.y),
                             fmaf(hv.z, dd, bv.z), fmaf(hv.w, dd, bv.w));
    for (int e = 0; e < d; e++) {
        int r = __ldg(&src[s0 + e]);
        float coef = dinv[r] * dc;
        float4 v = ((const float4*)(h + (long)r * Hd))[lane];
        acc.x = fmaf(v.x, coef, acc.x);
        acc.y = fmaf(v.y, coef, acc.y);
        acc.z = fmaf(v.z, coef, acc.z);
        acc.w = fmaf(v.w, coef, acc.w);
    }
    acc.x = fmaxf(acc.x, 0.f); acc.y = fmaxf(acc.y, 0.f);
    acc.z = fmaxf(acc.z, 0.f); acc.w = fmaxf(acc.w, 0.f);
    ((float4*)(out + (long)w * Hd))[lane] = acc;
}

// ------------------------------ scores -------------------------------------
__global__ void pnorm_k(const float* __restrict__ p) {     // <<<1,128>>>
    __shared__ float s[128];
    float v = p[threadIdx.x];
    s[threadIdx.x] = v * v;
    __syncthreads();
    for (int o = 64; o > 0; o >>= 1) {
        if (threadIdx.x < o) s[threadIdx.x] += s[threadIdx.x + o];
        __syncthreads();
    }
    if (threadIdx.x == 0) g_pinv = 1.0f / sqrtf(s[0]);
}
__global__ void score_k(const float* __restrict__ x, const float* __restrict__ p,
                        float* __restrict__ score, int n) {
    int w = (blockIdx.x * blockDim.x + threadIdx.x) >> 5;  // warp per node
    if (w >= n) return;
    int lane = threadIdx.x & 31;
    float4 v = ((const float4*)(x + (long)w * Hd))[lane];
    float4 q = ((const float4*)p)[lane];
    float s = v.x*q.x + v.y*q.y + v.z*q.z + v.w*q.w;
#pragma unroll
    for (int o = 16; o; o >>= 1) s += __shfl_xor_sync(0xffffffffu, s, o);
    if (lane == 0) score[w] = s * g_pinv;
}

// --------------------- top-k (matches jax.lax.top_k) ------------------------
__global__ void topk_k(const float* __restrict__ x, const float* __restrict__ score,
                       float* __restrict__ xs, int* __restrict__ newid,
                       int n_per, int k) {
    __shared__ unsigned long long keys[1024];
    int g = blockIdx.x, t = threadIdx.x;
    int base = g * n_per;

    newid[base + t] = -1;
    float s = score[base + t];
    unsigned int fb = __float_as_uint(s);
    unsigned int mp = (fb & 0x80000000u) ? ~fb : (fb | 0x80000000u); // order-preserving
    keys[t] = ((unsigned long long)(~mp) << 32) | (unsigned int)t;
    __syncthreads();

    for (int kk = 2; kk <= n_per; kk <<= 1) {
        for (int j = kk >> 1; j > 0; j >>= 1) {
            int ixj = t ^ j;
            if (ixj > t) {
                bool up = ((t & kk) == 0);
                unsigned long long a = keys[t], bq = keys[ixj];
                if ((a > bq) == up) { keys[t] = bq; keys[ixj] = a; }
            }
            __syncthreads();
        }
    }

    if (t < k) {
        int sel = (int)(keys[t] & 0xffffffffu);
        newid[base + sel] = g * k + t;
    }
    __syncthreads();

    int total = k * Hd;
    for (int idx = t; idx < total; idx += n_per) {
        int rank = idx >> 7, f = idx & 127;
        int sel = (int)(keys[rank] & 0xffffffffu);
        float tv = tanhf(score[base + sel]);
        xs[((long)(g * k + rank)) * Hd + f] = x[((long)(base + sel)) * Hd + f] * tv;
    }
}

// --------------------------- edge relabel ----------------------------------
__global__ void relabel_k(const int* __restrict__ row, const int* __restrict__ col,
                          const float* __restrict__ mask, const int* __restrict__ newid,
                          int* __restrict__ nrow, int* __restrict__ ncol,
                          float* __restrict__ nmask, int nE) {
    int e = blockIdx.x * blockDim.x + threadIdx.x;
    if (e >= nE) return;
    int nr = newid[row[e]], nc = newid[col[e]];
    float m = mask ? mask[e] : 1.0f;
    if (nr < 0 || nc < 0) m = 0.0f;
    nrow[e] = nr > 0 ? nr : 0;
    ncol[e] = nc > 0 ? nc : 0;
    nmask[e] = m;
}

// ------------------------------ readout ------------------------------------
__global__ void readout_k(const float* __restrict__ xs, float* __restrict__ out,
                          int k, int add) {                // <<<B,128>>>
    int g = blockIdx.x, f = threadIdx.x;
    float mx = -3.402823466e+38f, sm = 0.f;
    const float* p = xs + (long)g * k * Hd + f;
    for (int r = 0; r < k; r++) {
        float v = p[(long)r * Hd];
        mx = fmaxf(mx, v);
        sm += v;
    }
    float mean = sm / (float)k;
    if (add) { out[g*256 + f] += mx; out[g*256 + 128 + f] += mean; }
    else     { out[g*256 + f]  = mx; out[g*256 + 128 + f]  = mean; }
}

// ------------------------------- driver ------------------------------------
static inline int ceil_div(int a, int b) { return (a + b - 1) / b; }

struct Scratch {
    float *h, *cv, *xs1, *xs2, *xs3, *dinv, *sc, *m0, *m1;
    int *nid, *cnt, *start, *cursor, *bsum, *src, *r0, *c0, *r1, *c1;
};

static void run_layer(const Scratch& S, const float* xin, int n, int nper, int k,
                      const int* erow, const int* ecol, const float* emask,
                      const float* W, const float* b, const float* p,
                      float* xs_out, int* nrow, int* ncol, float* nmask,
                      int E, float* out, int addFlag)
{
    gemm128<<<n / 128, 256>>>(xin, W, S.h);

    cudaMemsetAsync(S.cnt, 0, n * sizeof(int));
    cudaMemsetAsync(S.cursor, 0, n * sizeof(int));
    hist_k<<<ceil_div(E, 256), 256>>>(ecol, emask, S.cnt, E);
    scanA_k<<<n / 1024, 1024>>>(S.cnt, S.start, S.bsum);
    scanB_k<<<1, 128>>>(S.bsum, n / 1024);
    scanC_k<<<ceil_div(n, 256), 256>>>(S.start, S.bsum, S.cnt, S.dinv, n);
    fill_k<<<ceil_div(E, 256), 256>>>(erow, ecol, emask, S.start, S.cursor, S.src, E);
    gather_k<<<ceil_div(n * 32, 256), 256>>>(S.h, S.start, S.cnt, S.src,
                                             S.dinv, b, S.cv, n);
    pnorm_k<<<1, 128>>>(p);
    score_k<<<ceil_div(n * 32, 256), 256>>>(S.cv, p, S.sc, n);
    topk_k<<<Bg, nper>>>(S.cv, S.sc, xs_out, S.nid, nper, k);
    if (nrow)
        relabel_k<<<ceil_div(E, 256), 256>>>(erow, ecol, emask, S.nid,
                                             nrow, ncol, nmask, E);
    readout_k<<<Bg, 128>>>(xs_out, out, k, addFlag);
}

extern "C" void kernel_launch(void* const* d_in, const int* in_sizes, int n_in,
                              void* d_out, int out_size)
{
    const float* x    = (const float*)d_in[0];
    const int*   erow = (const int*)  d_in[1];
    const int*   ecol = (const int*)  d_in[2];
    const float* W1 = (const float*)d_in[3],  *b1 = (const float*)d_in[4],  *p1 = (const float*)d_in[5];
    const float* W2 = (const float*)d_in[6],  *b2 = (const float*)d_in[7],  *p2 = (const float*)d_in[8];
    const float* W3 = (const float*)d_in[9],  *b3 = (const float*)d_in[10], *p3 = (const float*)d_in[11];
    float* out = (float*)d_out;
    const int E = in_sizes[1];

    Scratch S;
    cudaGetSymbolAddress((void**)&S.h,      g_h);
    cudaGetSymbolAddress((void**)&S.cv,     g_cv);
    cudaGetSymbolAddress((void**)&S.xs1,    g_xs1);
    cudaGetSymbolAddress((void**)&S.xs2,    g_xs2);
    cudaGetSymbolAddress((void**)&S.xs3,    g_xs3);
    cudaGetSymbolAddress((void**)&S.dinv,   g_dinv);
    cudaGetSymbolAddress((void**)&S.sc,     g_sc);
    cudaGetSymbolAddress((void**)&S.nid,    g_newid);
    cudaGetSymbolAddress((void**)&S.cnt,    g_cnt);
    cudaGetSymbolAddress((void**)&S.start,  g_start);
    cudaGetSymbolAddress((void**)&S.cursor, g_cursor);
    cudaGetSymbolAddress((void**)&S.bsum,   g_bsum);
    cudaGetSymbolAddress((void**)&S.src,    g_src);
    cudaGetSymbolAddress((void**)&S.r0,     g_r0);
    cudaGetSymbolAddress((void**)&S.c0,     g_c0);
    cudaGetSymbolAddress((void**)&S.m0,     g_m0);
    cudaGetSymbolAddress((void**)&S.r1,     g_r1);
    cudaGetSymbolAddress((void**)&S.c1,     g_c1);
    cudaGetSymbolAddress((void**)&S.m1,     g_m1);

    // Layer 1: 131072 nodes, 1024/graph -> keep 512
    run_layer(S, x, NN1, 1024, 512, erow, ecol, /*mask=*/nullptr,
              W1, b1, p1, S.xs1, S.r0, S.c0, S.m0, E, out, /*add=*/0);
    // Layer 2: 65536 nodes, 512/graph -> keep 256
    run_layer(S, S.xs1, NN2, 512, 256, S.r0, S.c0, S.m0,
              W2, b2, p2, S.xs2, S.r1, S.c1, S.m1, E, out, /*add=*/1);
    // Layer 3: 32768 nodes, 256/graph -> keep 128 (no relabel needed)
    run_layer(S, S.xs2, NN3, 256, 128, S.r1, S.c1, S.m1,
              W3, b3, p3, S.xs3, nullptr, nullptr, nullptr, E, out, /*add=*/1);
}

// round 3
// speedup vs baseline: 4.8269x; 1.0135x over previous
#include <cuda_runtime.h>
#include <cuda_bf16.h>
#include <math.h>

// ---------------------------------------------------------------------------
// GCN + TopK pooling stack (3 layers), B=128 graphs, N=1024 nodes, H=128.
// ---------------------------------------------------------------------------

#define Bg   128
#define Npg  1024
#define Hd   128
#define NN1  (Bg*Npg)        // 131072
#define NN2  (Bg*512)        // 65536
#define NN3  (Bg*256)        // 32768
#define EMAX 1048576

// ------------------------- device scratch (no allocs) ----------------------
__device__ __align__(128) float g_h [NN1*Hd];   // h = (x @ W) * dinv[row]
__device__ __align__(128) float g_cv[NN1*Hd];   // conv output (relu'd)
__device__ __align__(128) float g_xs1[NN2*Hd];
__device__ __align__(128) float g_xs2[NN3*Hd];
__device__ __align__(128) float g_xs3[(Bg*128)*Hd];
__device__ float g_dinv[NN1];
__device__ float g_sc[NN1];
__device__ int   g_newid[NN1];
__device__ int   g_cnt[NN1];      // in-degree counts
__device__ int   g_start[NN1];    // CSR start offsets
__device__ int   g_cursor[NN1];   // fill cursors
__device__ int   g_bsum[256];
__device__ int   g_src[EMAX];     // CSR source-node list
__device__ int   g_r0[EMAX], g_c0[EMAX];   // compacted edges after pool 1
__device__ int   g_r1[EMAX], g_c1[EMAX];   // compacted edges after pool 2
__device__ int   g_nE[2];         // surviving edge counts
__device__ float g_pinv[3];       // 1/||p_l||

// ------------------------------ f32x2 helpers -------------------------------
__device__ __forceinline__ unsigned long long pack2(float x) {
    unsigned long long r;
    asm("mov.b64 %0, {%1, %1};" : "=l"(r) : "f"(x));
    return r;
}
__device__ __forceinline__ unsigned long long pack2(float x, float y) {
    unsigned long long r;
    asm("mov.b64 %0, {%1, %2};" : "=l"(r) : "f"(x), "f"(y));
    return r;
}
__device__ __forceinline__ void fma2(unsigned long long& d,
                                     unsigned long long a, unsigned long long b) {
    asm("fma.rn.f32x2 %0, %1, %2, %0;" : "+l"(d) : "l"(a), "l"(b));
}

// ------------------------------- GEMM --------------------------------------
// Out[n,128] = (X[n,128] @ W[128,128]) * dinv[row].  128-row tiles, 8x8 micro.
#define KP 132

__global__ void __launch_bounds__(256, 2)
gemm128(const float* __restrict__ X, const float* __restrict__ W,
        const float* __restrict__ dinv, float* __restrict__ Out)
{
    __shared__ float sX[16][KP];   // [k][row]
    __shared__ float sW[16][KP];   // [k][col]
    const int tid = threadIdx.x;
    const int tx = tid & 15;
    const int ty = tid >> 4;
    const long row0 = (long)blockIdx.x * 128;

    unsigned long long acc[8][4];
#pragma unroll
    for (int i = 0; i < 8; i++)
#pragma unroll
        for (int j = 0; j < 4; j++) acc[i][j] = 0ull;

    for (int k0 = 0; k0 < 128; k0 += 16) {
#pragma unroll
        for (int q = 0; q < 2; q++) {
            int f = tid + q * 256;
            int kk = f >> 5, c4 = f & 31;
            float4 v = ((const float4*)(W + (k0 + kk) * 128))[c4];
            float* d = &sW[kk][c4 * 4];
            d[0] = v.x; d[1] = v.y; d[2] = v.z; d[3] = v.w;
        }
#pragma unroll
        for (int q = 0; q < 2; q++) {
            int f = tid + q * 256;
            int r = f >> 2, kq = (f & 3) * 4;
            float4 v = ((const float4*)(X + (row0 + r) * 128 + k0))[f & 3];
            sX[kq + 0][r] = v.x; sX[kq + 1][r] = v.y;
            sX[kq + 2][r] = v.z; sX[kq + 3][r] = v.w;
        }
        __syncthreads();

#pragma unroll
        for (int k = 0; k < 16; k++) {
            float4 b0 = *(const float4*)&sW[k][tx * 4];
            float4 b1 = *(const float4*)&sW[k][64 + tx * 4];
            float4 a0 = *(const float4*)&sX[k][ty * 8];
            float4 a1 = *(const float4*)&sX[k][ty * 8 + 4];
            unsigned long long B[4] = { pack2(b0.x, b0.y), pack2(b0.z, b0.w),
                                        pack2(b1.x, b1.y), pack2(b1.z, b1.w) };
            float av[8] = { a0.x, a0.y, a0.z, a0.w, a1.x, a1.y, a1.z, a1.w };
#pragma unroll
            for (int i = 0; i < 8; i++) {
                unsigned long long A = pack2(av[i]);
                fma2(acc[i][0], A, B[0]);
                fma2(acc[i][1], A, B[1]);
                fma2(acc[i][2], A, B[2]);
                fma2(acc[i][3], A, B[3]);
            }
        }
        __syncthreads();
    }

#pragma unroll
    for (int i = 0; i < 8; i++) {
        long row = row0 + ty * 8 + i;
        float dv = dinv[row];
        float* o = Out + row * 128;
        float2* a = (float2*)&acc[i][0];
        float4 v0 = make_float4(a[0].x * dv, a[0].y * dv, a[1].x * dv, a[1].y * dv);
        float4 v1 = make_float4(a[2].x * dv, a[2].y * dv, a[3].x * dv, a[3].y * dv);
        *((float4*)(o + tx * 4))      = v0;
        *((float4*)(o + 64 + tx * 4)) = v1;
    }
}

// ------------------------- CSR build: hist / scan ---------------------------
__global__ void hist_k(const int* __restrict__ col, int* __restrict__ cnt, int nE) {
    int i = blockIdx.x * blockDim.x + threadIdx.x;
    if (i < nE) atomicAdd(&cnt[col[i]], 1);
}

__global__ void scanA_k(const int* __restrict__ cnt, int* __restrict__ start,
                        int* __restrict__ bsum) {
    __shared__ int s[1024];
    int t = threadIdx.x;
    int i = blockIdx.x * 1024 + t;
    int v = cnt[i];
    s[t] = v;
    __syncthreads();
    for (int o = 1; o < 1024; o <<= 1) {
        int add = (t >= o) ? s[t - o] : 0;
        __syncthreads();
        s[t] += add;
        __syncthreads();
    }
    start[i] = s[t] - v;
    if (t == 1023) bsum[blockIdx.x] = s[t];
}

__global__ void scanB_k(int* bsum, int nb) {   // <<<1,128>>>, nb <= 128
    __shared__ int s[128];
    int t = threadIdx.x;
    int v = (t < nb) ? bsum[t] : 0;
    s[t] = v;
    __syncthreads();
    for (int o = 1; o < 128; o <<= 1) {
        int add = (t >= o) ? s[t - o] : 0;
        __syncthreads();
        s[t] += add;
        __syncthreads();
    }
    if (t < nb) bsum[t] = s[t] - v;
}

__global__ void scanC_k(int* __restrict__ start, const int* __restrict__ bsum,
                        const int* __restrict__ cnt, float* __restrict__ dinv, int n) {
    int i = blockIdx.x * blockDim.x + threadIdx.x;
    if (i >= n) return;
    start[i] += bsum[i >> 10];
    dinv[i] = rsqrtf((float)cnt[i] + 1.0f);
}

__global__ void fill_k(const int* __restrict__ row, const int* __restrict__ col,
                       const int* __restrict__ start, int* __restrict__ cursor,
                       int* __restrict__ src, const int* __restrict__ boundPtr,
                       int maxE) {
    int i = blockIdx.x * blockDim.x + threadIdx.x;
    int bound = boundPtr ? __ldg(boundPtr) : maxE;
    if (i >= bound) return;
    int c = col[i];
    int p = atomicAdd(&cursor[c], 1);
    src[start[c] + p] = row[i];
}

// ---- gather (h is dinv-prescaled) + self + bias + relu + score, fused ------
__global__ void gather_k(const float* __restrict__ h, const int* __restrict__ start,
                         const int* __restrict__ cnt, const int* __restrict__ src,
                         const float* __restrict__ dinv, const float* __restrict__ b,
                         const float* __restrict__ p, const float* __restrict__ pinv,
                         float* __restrict__ out, float* __restrict__ score, int n) {
    int w = (blockIdx.x * blockDim.x + threadIdx.x) >> 5;
    if (w >= n) return;
    int lane = threadIdx.x & 31;
    float dc = dinv[w];
    int s0 = start[w], d = cnt[w];
    float4 acc = ((const float4*)(h + (long)w * Hd))[lane];  // self term (prescaled)
    for (int e = 0; e < d; e++) {
        int r = __ldg(&src[s0 + e]);
        float4 v = ((const float4*)(h + (long)r * Hd))[lane];
        acc.x += v.x; acc.y += v.y; acc.z += v.z; acc.w += v.w;
    }
    float4 bv = ((const float4*)b)[lane];
    acc.x = fmaxf(fmaf(acc.x, dc, bv.x), 0.f);
    acc.y = fmaxf(fmaf(acc.y, dc, bv.y), 0.f);
    acc.z = fmaxf(fmaf(acc.z, dc, bv.z), 0.f);
    acc.w = fmaxf(fmaf(acc.w, dc, bv.w), 0.f);
    ((float4*)(out + (long)w * Hd))[lane] = acc;
    // fused score = dot(x, p) * (1/||p||)
    float4 pv = ((const float4*)p)[lane];
    float s = acc.x*pv.x + acc.y*pv.y + acc.z*pv.z + acc.w*pv.w;
#pragma unroll
    for (int o = 16; o; o >>= 1) s += __shfl_xor_sync(0xffffffffu, s, o);
    if (lane == 0) score[w] = s * __ldg(pinv);
}

// ------------------------------ p norms (all 3) -----------------------------
__global__ void pnorm3_k(const float* __restrict__ p1, const float* __restrict__ p2,
                         const float* __restrict__ p3) {   // <<<3,128>>>
    __shared__ float s[128];
    const float* p = (blockIdx.x == 0) ? p1 : (blockIdx.x == 1) ? p2 : p3;
    float v = p[threadIdx.x];
    s[threadIdx.x] = v * v;
    __syncthreads();
    for (int o = 64; o > 0; o >>= 1) {
        if (threadIdx.x < o) s[threadIdx.x] += s[threadIdx.x + o];
        __syncthreads();
    }
    if (threadIdx.x == 0) g_pinv[blockIdx.x] = rsqrtf(s[0]);
}

// ------- top-k (matches jax.lax.top_k) + readout + next-layer zeroing -------
__global__ void topk_k(const float* __restrict__ x, const float* __restrict__ score,
                       float* __restrict__ xs, int* __restrict__ newid,
                       int n_per, int k,
                       float* __restrict__ out, int addFlag,
                       int* __restrict__ cnt_next, int* __restrict__ cursor_next,
                       int* __restrict__ counter_next, int n_next) {
    __shared__ unsigned long long keys[1024];
    int g = blockIdx.x, t = threadIdx.x;
    int base = g * n_per;
    int gid = base + t;

    // fused zero-init for next layer's CSR build
    if (n_next > 0) {
        if (gid < n_next) { cnt_next[gid] = 0; cursor_next[gid] = 0; }
        if (gid == 0) *counter_next = 0;
    }

    newid[gid] = -1;
    float s = score[gid];
    unsigned int fb = __float_as_uint(s);
    unsigned int mp = (fb & 0x80000000u) ? ~fb : (fb | 0x80000000u);
    keys[t] = ((unsigned long long)(~mp) << 32) | (unsigned int)t;
    __syncthreads();

    for (int kk = 2; kk <= n_per; kk <<= 1) {
        for (int j = kk >> 1; j > 0; j >>= 1) {
            int ixj = t ^ j;
            if (ixj > t) {
                bool up = ((t & kk) == 0);
                unsigned long long a = keys[t], bq = keys[ixj];
                if ((a > bq) == up) { keys[t] = bq; keys[ixj] = a; }
            }
            __syncthreads();
        }
    }

    if (t < k) {
        int sel = (int)(keys[t] & 0xffffffffu);
        newid[base + sel] = g * k + t;
    }
    __syncthreads();

    int total = k * Hd;
    for (int idx = t; idx < total; idx += n_per) {
        int rank = idx >> 7, f = idx & 127;
        int sel = (int)(keys[rank] & 0xffffffffu);
        float tv = tanhf(score[base + sel]);
        xs[((long)(g * k + rank)) * Hd + f] = x[((long)(base + sel)) * Hd + f] * tv;
    }
    __syncthreads();

    // fused readout: cat([max, mean]) over this graph's k rows
    if (t < 128) {
        const float* pr = xs + (long)g * k * Hd + t;
        float mx = -3.402823466e+38f, sm = 0.f;
        for (int r = 0; r < k; r++) {
            float v = pr[(long)r * Hd];
            mx = fmaxf(mx, v);
            sm += v;
        }
        float mean = sm / (float)k;
        if (addFlag) { out[g*256 + t] += mx; out[g*256 + 128 + t] += mean; }
        else         { out[g*256 + t]  = mx; out[g*256 + 128 + t]  = mean; }
    }
}

// ---- edge compaction (relabel + filter) + histogram of next layer ----------
__global__ void compact_k(const int* __restrict__ row, const int* __restrict__ col,
                          const int* __restrict__ newid,
                          int* __restrict__ orow, int* __restrict__ ocol,
                          int* __restrict__ cnt_next, int* __restrict__ counter,
                          const int* __restrict__ boundPtr, int maxE) {
    int e = blockIdx.x * blockDim.x + threadIdx.x;
    int bound = boundPtr ? __ldg(boundPtr) : maxE;
    bool valid = (e < bound);
    int nr = -1, nc = -1;
    if (valid) {
        nr = newid[row[e]];
        nc = newid[col[e]];
        valid = (nr >= 0) && (nc >= 0);
    }
    unsigned m = __ballot_sync(0xffffffffu, valid);
    if (valid) {
        int lane = threadIdx.x & 31;
        int leader = __ffs(m) - 1;
        int prefix = __popc(m & ((1u << lane) - 1u));
        int basep = 0;
        if (lane == leader) basep = atomicAdd(counter, __popc(m));
        basep = __shfl_sync(m, basep, leader);
        int pos = basep + prefix;
        orow[pos] = nr;
        ocol[pos] = nc;
        atomicAdd(&cnt_next[nc], 1);
    }
}

// ------------------------------- driver ------------------------------------
static inline int ceil_div(int a, int b) { return (a + b - 1) / b; }

struct Scratch {
    float *h, *cv, *xs1, *xs2, *xs3, *dinv, *sc, *pinv;
    int *nid, *cnt, *start, *cursor, *bsum, *src, *r0, *c0, *r1, *c1, *nE;
};

static void csr_and_conv(const Scratch& S, const float* xin, int n,
                         const int* erow, const int* ecol,
                         const int* boundPtr, int maxE,
                         const float* W, const float* b, const float* p, int layer)
{
    scanA_k<<<n / 1024, 1024>>>(S.cnt, S.start, S.bsum);
    scanB_k<<<1, 128>>>(S.bsum, n / 1024);
    scanC_k<<<ceil_div(n, 256), 256>>>(S.start, S.bsum, S.cnt, S.dinv, n);
    gemm128<<<n / 128, 256>>>(xin, W, S.dinv, S.h);
    fill_k<<<ceil_div(maxE, 256), 256>>>(erow, ecol, S.start, S.cursor, S.src,
                                         boundPtr, maxE);
    gather_k<<<ceil_div(n * 32, 256), 256>>>(S.h, S.start, S.cnt, S.src,
                                             S.dinv, b, p, S.pinv + layer,
                                             S.cv, S.sc, n);
}

extern "C" void kernel_launch(void* const* d_in, const int* in_sizes, int n_in,
                              void* d_out, int out_size)
{
    const float* x    = (const float*)d_in[0];
    const int*   erow = (const int*)  d_in[1];
    const int*   ecol = (const int*)  d_in[2];
    const float* W1 = (const float*)d_in[3],  *b1 = (const float*)d_in[4],  *p1 = (const float*)d_in[5];
    const float* W2 = (const float*)d_in[6],  *b2 = (const float*)d_in[7],  *p2 = (const float*)d_in[8];
    const float* W3 = (const float*)d_in[9],  *b3 = (const float*)d_in[10], *p3 = (const float*)d_in[11];
    float* out = (float*)d_out;
    const int E = in_sizes[1];

    Scratch S;
    cudaGetSymbolAddress((void**)&S.h,      g_h);
    cudaGetSymbolAddress((void**)&S.cv,     g_cv);
    cudaGetSymbolAddress((void**)&S.xs1,    g_xs1);
    cudaGetSymbolAddress((void**)&S.xs2,    g_xs2);
    cudaGetSymbolAddress((void**)&S.xs3,    g_xs3);
    cudaGetSymbolAddress((void**)&S.dinv,   g_dinv);
    cudaGetSymbolAddress((void**)&S.sc,     g_sc);
    cudaGetSymbolAddress((void**)&S.pinv,   g_pinv);
    cudaGetSymbolAddress((void**)&S.nid,    g_newid);
    cudaGetSymbolAddress((void**)&S.cnt,    g_cnt);
    cudaGetSymbolAddress((void**)&S.start,  g_start);
    cudaGetSymbolAddress((void**)&S.cursor, g_cursor);
    cudaGetSymbolAddress((void**)&S.bsum,   g_bsum);
    cudaGetSymbolAddress((void**)&S.src,    g_src);
    cudaGetSymbolAddress((void**)&S.r0,     g_r0);
    cudaGetSymbolAddress((void**)&S.c0,     g_c0);
    cudaGetSymbolAddress((void**)&S.r1,     g_r1);
    cudaGetSymbolAddress((void**)&S.c1,     g_c1);
    cudaGetSymbolAddress((void**)&S.nE,     g_nE);

    pnorm3_k<<<3, 128>>>(p1, p2, p3);

    // ---------------- Layer 1: n=131072, keep 512/1024 ----------------
    cudaMemsetAsync(S.cnt, 0, NN1 * sizeof(int));
    cudaMemsetAsync(S.cursor, 0, NN1 * sizeof(int));
    hist_k<<<ceil_div(E, 256), 256>>>(ecol, S.cnt, E);
    csr_and_conv(S, x, NN1, erow, ecol, nullptr, E, W1, b1, p1, 0);
    topk_k<<<Bg, 1024>>>(S.cv, S.sc, S.xs1, S.nid, 1024, 512, out, 0,
                         S.cnt, S.cursor, S.nE + 0, NN2);
    compact_k<<<ceil_div(E, 256), 256>>>(erow, ecol, S.nid, S.r0, S.c0,
                                         S.cnt, S.nE + 0, nullptr, E);

    // ---------------- Layer 2: n=65536, keep 256/512 ----------------
    csr_and_conv(S, S.xs1, NN2, S.r0, S.c0, S.nE + 0, E, W2, b2, p2, 1);
    topk_k<<<Bg, 512>>>(S.cv, S.sc, S.xs2, S.nid, 512, 256, out, 1,
                        S.cnt, S.cursor, S.nE + 1, NN3);
    compact_k<<<ceil_div(E, 256), 256>>>(S.r0, S.c0, S.nid, S.r1, S.c1,
                                         S.cnt, S.nE + 1, S.nE + 0, E);

    // ---------------- Layer 3: n=32768, keep 128/256 ----------------
    csr_and_conv(S, S.xs2, NN3, S.r1, S.c1, S.nE + 1, E, W3, b3, p3, 2);
    topk_k<<<Bg, 256>>>(S.cv, S.sc, S.xs3, S.nid, 256, 128, out, 1,
                        nullptr, nullptr, nullptr, 0);
}